// round 13
// baseline (speedup 1.0000x reference)
#include <cuda_runtime.h>
#include <cstdint>

// Output: [B=16, T=50, H=100, W=100, P=25] fp32 = 200M elems = 800MB.
// R13 experiment: WRITE-THROUGH zero-fill (__stwt / ST.E.WT) instead of
// streaming write-back (__stcs). Hypothesis: avoids L2 dirty-line
// accumulation + end-of-kernel drain on an 800MB pure write stream.
// Structure otherwise identical to the best-measured R9 kernel:
// single launch, 48829 free-running CTAs, one CTA-scope barrier each,
// slice-local exactly-once scatter of the 20k ones.

static constexpr int B = 16;
static constexpr int T = 50;
static constexpr int H = 100;
static constexpr int W = 100;
static constexpr int P = 25;
static constexpr unsigned BT_STRIDE = (unsigned)H * W * P;   // 250000

static constexpr int VPT = 4;                        // float4s per thread (64B)
static constexpr int ZTHREADS = 256;
static constexpr unsigned SLICE = ZTHREADS * VPT * 4;        // 4096 floats

__global__ void __launch_bounds__(ZTHREADS)
fused_raster_kernel(const float2* __restrict__ x,          // [B*T*P] (px,py)
                    const float2* __restrict__ resolution, // [B*T]
                    const float2* __restrict__ origin,     // [B*T]
                    float* __restrict__ out,
                    unsigned n_vec4) {
    // ---- Phase 2a (pre-barrier): compute this slice's candidate one-write.
    //      Touches only inputs, never `out` -> no hazard with the zeros.
    const unsigned n = n_vec4 * 4u;                  // 200,000,000 < 2^31
    const unsigned s = blockIdx.x * SLICE;
    const unsigned e = (s + SLICE < n) ? (s + SLICE) : n;

    const unsigned bt0 = s / BT_STRIDE;              // const-div -> mul/shift
    const unsigned bt1 = (e - 1u) / BT_STRIDE;       // slice spans <=2 regions
    const unsigned nbt = bt1 - bt0 + 1u;             // 1 or 2

    const unsigned w = threadIdx.x >> 5;
    const unsigned l = threadIdx.x & 31u;

    bool     do_write = false;
    unsigned off      = 0;
    if (w < nbt && l < (unsigned)P) {
        const unsigned bt = bt0 + w;
        const float2 pt = __ldg(&x[bt * P + l]);     // (px, py)
        const float2 rs = __ldg(&resolution[bt]);
        const float2 og = __ldg(&origin[bt]);

        const int col = (int)(pt.x / rs.x + og.x);   // trunc == astype(int)
        const int row = (int)(pt.y / rs.y + og.y);

        if (row >= 0 && row < H && col >= 0 && col < W) {   // JAX drops OOB
            off = ((bt * (unsigned)H + (unsigned)row) * (unsigned)W
                       + (unsigned)col) * (unsigned)P + l;
            do_write = (off >= s && off < e);
        }
    }

    // ---- Phase 1: zero this block's slice (4x ST.E.128.WT write-through) ----
    const float4 z = make_float4(0.f, 0.f, 0.f, 0.f);
    const unsigned base = blockIdx.x * (ZTHREADS * VPT) + threadIdx.x;
#pragma unroll
    for (int k = 0; k < VPT; k++) {
        unsigned i = base + k * ZTHREADS;
        if (i < n_vec4) {
            __stwt(reinterpret_cast<float4*>(out) + i, z);
        }
    }

    // CTA-scope ordering: this block's zeros precede its ones.
    __syncthreads();

    // ---- Phase 2b (post-barrier): single store, ~5cyc tail ----
    if (do_write) {
        out[off] = 1.0f;
    }
}

// ---------------------------------------------------------------------------
extern "C" void kernel_launch(void* const* d_in, const int* in_sizes, int n_in,
                              void* d_out, int out_size) {
    const float2* x          = (const float2*)d_in[0];
    const float2* resolution = (const float2*)d_in[1];
    const float2* origin     = (const float2*)d_in[2];
    float* out = (float*)d_out;

    const unsigned n = (unsigned)out_size;           // 200,000,000 (div by 4)
    const unsigned n_vec4 = n / 4u;                  // 50,000,000

    const unsigned slots = (n_vec4 + VPT - 1) / VPT;
    const unsigned blocks = (slots + ZTHREADS - 1) / ZTHREADS;   // 48829

    fused_raster_kernel<<<blocks, ZTHREADS>>>(x, resolution, origin, out, n_vec4);
}

// round 14
// speedup vs baseline: 1.0047x; 1.0047x over previous
#include <cuda_runtime.h>
#include <cstdint>

// Output: [B=16, T=50, H=100, W=100, P=25] fp32 = 200M elems = 800MB.
// R14 experiment: 256-bit stores (st.global.cs.v8.f32 -> STG.E.256) for the
// zero fill — 2x32B per thread instead of 4x16B. Halves STG count and L1tex
// wavefront insertions per byte. Structure otherwise identical to the
// best-measured kernel: single launch, 48829 free-running CTAs, one CTA-scope
// barrier, slice-local exactly-once scatter of the 20k ones.

static constexpr int B = 16;
static constexpr int T = 50;
static constexpr int H = 100;
static constexpr int W = 100;
static constexpr int P = 25;
static constexpr unsigned BT_STRIDE = (unsigned)H * W * P;   // 250000

static constexpr int ZTHREADS = 256;
static constexpr int CPT = 2;                        // 32B chunks per thread
static constexpr unsigned SLICE = ZTHREADS * CPT * 8;        // 4096 floats
static constexpr unsigned SLICE_CH = ZTHREADS * CPT;         // 512 chunks/block

__device__ __forceinline__ void st256_zero_cs(float* p) {
    asm volatile(
        "st.global.cs.v8.f32 [%0], {%1, %1, %1, %1, %1, %1, %1, %1};"
        :: "l"(p), "f"(0.0f) : "memory");
}

__global__ void __launch_bounds__(ZTHREADS)
fused_raster_kernel(const float2* __restrict__ x,          // [B*T*P] (px,py)
                    const float2* __restrict__ resolution, // [B*T]
                    const float2* __restrict__ origin,     // [B*T]
                    float* __restrict__ out,
                    unsigned n_chunks) {                   // n/8 = 25,000,000
    // ---- Phase 2a (pre-barrier): compute this slice's candidate one-write.
    const unsigned n = n_chunks * 8u;                // 200,000,000 < 2^31
    const unsigned s = blockIdx.x * SLICE;
    const unsigned e = (s + SLICE < n) ? (s + SLICE) : n;

    const unsigned bt0 = s / BT_STRIDE;              // const-div -> mul/shift
    const unsigned bt1 = (e - 1u) / BT_STRIDE;       // slice spans <=2 regions
    const unsigned nbt = bt1 - bt0 + 1u;             // 1 or 2

    const unsigned w = threadIdx.x >> 5;
    const unsigned l = threadIdx.x & 31u;

    bool     do_write = false;
    unsigned off      = 0;
    if (w < nbt && l < (unsigned)P) {
        const unsigned bt = bt0 + w;
        const float2 pt = __ldg(&x[bt * P + l]);     // (px, py)
        const float2 rs = __ldg(&resolution[bt]);
        const float2 og = __ldg(&origin[bt]);

        const int col = (int)(pt.x / rs.x + og.x);   // trunc == astype(int)
        const int row = (int)(pt.y / rs.y + og.y);

        if (row >= 0 && row < H && col >= 0 && col < W) {   // JAX drops OOB
            off = ((bt * (unsigned)H + (unsigned)row) * (unsigned)W
                       + (unsigned)col) * (unsigned)P + l;
            do_write = (off >= s && off < e);
        }
    }

    // ---- Phase 1: zero this block's slice (2x STG.E.256, evict-first) ----
    const unsigned base = blockIdx.x * SLICE_CH + threadIdx.x;
#pragma unroll
    for (int k = 0; k < CPT; k++) {
        unsigned c = base + k * ZTHREADS;            // 32B chunk index
        if (c < n_chunks) {
            st256_zero_cs(out + (size_t)c * 8u);
        }
    }

    // CTA-scope ordering: this block's zeros precede its ones.
    __syncthreads();

    // ---- Phase 2b (post-barrier): single store, ~5cyc tail ----
    if (do_write) {
        out[off] = 1.0f;
    }
}

// ---------------------------------------------------------------------------
extern "C" void kernel_launch(void* const* d_in, const int* in_sizes, int n_in,
                              void* d_out, int out_size) {
    const float2* x          = (const float2*)d_in[0];
    const float2* resolution = (const float2*)d_in[1];
    const float2* origin     = (const float2*)d_in[2];
    float* out = (float*)d_out;

    const unsigned n = (unsigned)out_size;           // 200,000,000 (div by 8)
    const unsigned n_chunks = n / 8u;                // 25,000,000

    const unsigned blocks = (n_chunks + SLICE_CH - 1) / SLICE_CH;   // 48829

    fused_raster_kernel<<<blocks, ZTHREADS>>>(x, resolution, origin, out,
                                              n_chunks);
}

// round 15
// speedup vs baseline: 1.0137x; 1.0090x over previous
#include <cuda_runtime.h>
#include <cstdint>

// RasterPoints — FINAL KERNEL (best measured: 106.94us; kernel 105.5us @
// 88.6% DRAM = 7.0 TB/s, the pure-write-stream roofline of this part).
//
// Output: [B=16, T=50, H=100, W=100, P=25] fp32 = 200M elems = 800MB, of
// which exactly B*T*P = 20000 elements are 1.0f. The problem is an 800MB
// write stream + tiny scatter; DRAM write bandwidth is the only binding
// resource (issue 14%, ALU 8%, FMA 5%, L2 63% in ncu).
//
// Design (validated over 14 rounds):
//  * SINGLE launch — any second kernel costs ≥4us of launch/ramp overhead.
//  * 48829 free-running CTAs, each owning one contiguous 4096-float slice.
//    (Persistent grids with per-tile barriers lock-step the store stream:
//     -11us. Per-CTA global release fences serialize writeback: -181us.)
//  * Each block: zero its slice with 4x STG.128 evict-first streaming
//    stores; ONE __syncthreads (CTA-scope ordering only); then write the
//    <=50 candidate 1.0f points of the <=2 bt-regions overlapping the slice
//    (each bt region = H*W*P = 250000 elems spans many slices; each bt has
//    exactly P=25 points). Candidates are computed BEFORE the barrier so
//    their input loads hide under the store stream.
//  * Every output offset belongs to exactly one slice -> exactly-once,
//    race-free, deterministic, graph-capturable, allocation-free.

static constexpr int B = 16;
static constexpr int T = 50;
static constexpr int H = 100;
static constexpr int W = 100;
static constexpr int P = 25;
static constexpr unsigned BT_STRIDE = (unsigned)H * W * P;   // 250000

static constexpr int VPT = 4;                        // float4s per thread (64B)
static constexpr int ZTHREADS = 256;
static constexpr unsigned SLICE = ZTHREADS * VPT * 4;        // 4096 floats

__global__ void __launch_bounds__(ZTHREADS)
fused_raster_kernel(const float2* __restrict__ x,          // [B*T*P] (px,py)
                    const float2* __restrict__ resolution, // [B*T]
                    const float2* __restrict__ origin,     // [B*T]
                    float* __restrict__ out,
                    unsigned n_vec4) {
    // ---- Phase 2a (pre-barrier): compute this slice's candidate one-write.
    //      Touches only inputs, never `out` -> no hazard with the zeros.
    const unsigned n = n_vec4 * 4u;                  // 200,000,000 < 2^31
    const unsigned s = blockIdx.x * SLICE;
    const unsigned e = (s + SLICE < n) ? (s + SLICE) : n;

    const unsigned bt0 = s / BT_STRIDE;              // const-div -> mul/shift
    const unsigned bt1 = (e - 1u) / BT_STRIDE;       // slice spans <=2 regions
    const unsigned nbt = bt1 - bt0 + 1u;             // 1 or 2

    const unsigned w = threadIdx.x >> 5;
    const unsigned l = threadIdx.x & 31u;

    bool     do_write = false;
    unsigned off      = 0;
    if (w < nbt && l < (unsigned)P) {
        const unsigned bt = bt0 + w;
        const float2 pt = __ldg(&x[bt * P + l]);     // (px, py)
        const float2 rs = __ldg(&resolution[bt]);
        const float2 og = __ldg(&origin[bt]);

        const int col = (int)(pt.x / rs.x + og.x);   // trunc == astype(int)
        const int row = (int)(pt.y / rs.y + og.y);

        if (row >= 0 && row < H && col >= 0 && col < W) {   // JAX drops OOB
            off = ((bt * (unsigned)H + (unsigned)row) * (unsigned)W
                       + (unsigned)col) * (unsigned)P + l;
            do_write = (off >= s && off < e);
        }
    }

    // ---- Phase 1: zero this block's slice (4x STG.128, evict-first) ----
    const float4 z = make_float4(0.f, 0.f, 0.f, 0.f);
    const unsigned base = blockIdx.x * (ZTHREADS * VPT) + threadIdx.x;
#pragma unroll
    for (int k = 0; k < VPT; k++) {
        unsigned i = base + k * ZTHREADS;
        if (i < n_vec4) {
            __stcs(reinterpret_cast<float4*>(out) + i, z);
        }
    }

    // CTA-scope ordering: this block's zeros precede its ones.
    __syncthreads();

    // ---- Phase 2b (post-barrier): single store, ~5cyc tail ----
    if (do_write) {
        out[off] = 1.0f;
    }
}

// ---------------------------------------------------------------------------
extern "C" void kernel_launch(void* const* d_in, const int* in_sizes, int n_in,
                              void* d_out, int out_size) {
    const float2* x          = (const float2*)d_in[0];
    const float2* resolution = (const float2*)d_in[1];
    const float2* origin     = (const float2*)d_in[2];
    float* out = (float*)d_out;

    const unsigned n = (unsigned)out_size;           // 200,000,000 (div by 4)
    const unsigned n_vec4 = n / 4u;                  // 50,000,000

    const unsigned slots = (n_vec4 + VPT - 1) / VPT;
    const unsigned blocks = (slots + ZTHREADS - 1) / ZTHREADS;   // 48829

    fused_raster_kernel<<<blocks, ZTHREADS>>>(x, resolution, origin, out, n_vec4);
}

// round 16
// speedup vs baseline: 1.0162x; 1.0024x over previous
#include <cuda_runtime.h>
#include <cstdint>

// RasterPoints — R16: thread-shape experiment. Identical algorithm and slice
// partition to the final kernel (4096-float slices, exactly-once slice-local
// scatter, one CTA-scope barrier, STG.128.CS zero fill), but 512-thread CTAs
// with VPT=2 instead of 256/VPT=4. Probes whether fatter CTAs change L1tex
// store-queue contention / wave spread. Predicted neutral (DRAM-capped).
//
// Output: [B=16, T=50, H=100, W=100, P=25] fp32 = 200M elems = 800MB.

static constexpr int B = 16;
static constexpr int T = 50;
static constexpr int H = 100;
static constexpr int W = 100;
static constexpr int P = 25;
static constexpr unsigned BT_STRIDE = (unsigned)H * W * P;   // 250000

static constexpr int VPT = 2;                        // float4s per thread (32B)
static constexpr int ZTHREADS = 512;
static constexpr unsigned SLICE = ZTHREADS * VPT * 4;        // 4096 floats

__global__ void __launch_bounds__(ZTHREADS)
fused_raster_kernel(const float2* __restrict__ x,          // [B*T*P] (px,py)
                    const float2* __restrict__ resolution, // [B*T]
                    const float2* __restrict__ origin,     // [B*T]
                    float* __restrict__ out,
                    unsigned n_vec4) {
    // ---- Phase 2a (pre-barrier): compute this slice's candidate one-write.
    //      Touches only inputs, never `out` -> no hazard with the zeros.
    const unsigned n = n_vec4 * 4u;                  // 200,000,000 < 2^31
    const unsigned s = blockIdx.x * SLICE;
    const unsigned e = (s + SLICE < n) ? (s + SLICE) : n;

    const unsigned bt0 = s / BT_STRIDE;              // const-div -> mul/shift
    const unsigned bt1 = (e - 1u) / BT_STRIDE;       // slice spans <=2 regions
    const unsigned nbt = bt1 - bt0 + 1u;             // 1 or 2

    const unsigned w = threadIdx.x >> 5;
    const unsigned l = threadIdx.x & 31u;

    bool     do_write = false;
    unsigned off      = 0;
    if (w < nbt && l < (unsigned)P) {
        const unsigned bt = bt0 + w;
        const float2 pt = __ldg(&x[bt * P + l]);     // (px, py)
        const float2 rs = __ldg(&resolution[bt]);
        const float2 og = __ldg(&origin[bt]);

        const int col = (int)(pt.x / rs.x + og.x);   // trunc == astype(int)
        const int row = (int)(pt.y / rs.y + og.y);

        if (row >= 0 && row < H && col >= 0 && col < W) {   // JAX drops OOB
            off = ((bt * (unsigned)H + (unsigned)row) * (unsigned)W
                       + (unsigned)col) * (unsigned)P + l;
            do_write = (off >= s && off < e);
        }
    }

    // ---- Phase 1: zero this block's slice (2x STG.128, evict-first) ----
    const float4 z = make_float4(0.f, 0.f, 0.f, 0.f);
    const unsigned base = blockIdx.x * (ZTHREADS * VPT) + threadIdx.x;
#pragma unroll
    for (int k = 0; k < VPT; k++) {
        unsigned i = base + k * ZTHREADS;
        if (i < n_vec4) {
            __stcs(reinterpret_cast<float4*>(out) + i, z);
        }
    }

    // CTA-scope ordering: this block's zeros precede its ones.
    __syncthreads();

    // ---- Phase 2b (post-barrier): single store, ~5cyc tail ----
    if (do_write) {
        out[off] = 1.0f;
    }
}

// ---------------------------------------------------------------------------
extern "C" void kernel_launch(void* const* d_in, const int* in_sizes, int n_in,
                              void* d_out, int out_size) {
    const float2* x          = (const float2*)d_in[0];
    const float2* resolution = (const float2*)d_in[1];
    const float2* origin     = (const float2*)d_in[2];
    float* out = (float*)d_out;

    const unsigned n = (unsigned)out_size;           // 200,000,000 (div by 4)
    const unsigned n_vec4 = n / 4u;                  // 50,000,000

    const unsigned slots = (n_vec4 + VPT - 1) / VPT; // 25,000,000
    const unsigned blocks = (slots + ZTHREADS - 1) / ZTHREADS;   // 48829

    fused_raster_kernel<<<blocks, ZTHREADS>>>(x, resolution, origin, out, n_vec4);
}